// round 7
// baseline (speedup 1.0000x reference)
#include <cuda_runtime.h>
#include <math.h>
#include <stdint.h>

#define Bsz 512
#define HH 84
#define WW 84
#define KOBJ 20
#define DEPTH 24
#define EMB 512

// ---------------- scratch (static device globals; no allocations) ----------------
__device__ float g_h1[Bsz * 32 * 20 * 20];          // conv1 out
__device__ float g_h2[Bsz * 64 * 9 * 9];            // conv2 out
__device__ float g_h3[Bsz * 64 * 7 * 7];            // conv3 out / feat
__device__ float g_fcpart[7 * Bsz * EMB];           // fc split-K partials
__device__ float g_x [Bsz * EMB];                   // fc out
__device__ float g_ot[Bsz * KOBJ * 2];
__device__ float g_ct[Bsz * 2];
__device__ float g_m21 [Bsz * DEPTH * 21 * 21];
__device__ float g_m42b[Bsz * DEPTH * 42 * 42];
__device__ float g_m84b[Bsz * DEPTH * 84 * 84];

__device__ __forceinline__ uint32_t cvt_tf32(float f) {
    uint32_t u;
    asm("cvt.rna.tf32.f32 %0, %1;" : "=r"(u) : "f"(f));
    return u;
}

__device__ __forceinline__ void mma_tf32(float c[4], const uint32_t a[4],
                                         uint32_t b0, uint32_t b1) {
    asm volatile("mma.sync.aligned.m16n8k8.row.col.f32.tf32.tf32.f32 "
        "{%0,%1,%2,%3}, {%4,%5,%6,%7}, {%8,%9}, {%0,%1,%2,%3};"
        : "+f"(c[0]), "+f"(c[1]), "+f"(c[2]), "+f"(c[3])
        : "r"(a[0]), "r"(a[1]), "r"(a[2]), "r"(a[3]), "r"(b0), "r"(b1));
}

// ---------------- conv1: [B,2,84,84] k8 s4 -> [B,32,20,20], relu ----------------
__global__ __launch_bounds__(256) void k_conv1(const float* __restrict__ inp,
                                               const float* __restrict__ w,
                                               const float* __restrict__ bias) {
    extern __shared__ float sm[];
    float* sIn = sm;          // 14112
    float* sW  = sm + 14112;  // 4096
    int b = blockIdx.x, tid = threadIdx.x;
    const float* ip = inp + b * 14112;
    for (int i = tid; i < 14112; i += 256) sIn[i] = ip[i];
    for (int i = tid; i < 4096;  i += 256) sW[i]  = w[i];
    __syncthreads();
    for (int o = tid; o < 3200; o += 256) {
        int oc = o / 100; int r = o % 100;
        int oy = (r / 10) * 2, ox = (r % 10) * 2;
        float a00 = 0.f, a01 = 0.f, a10 = 0.f, a11 = 0.f;
        for (int ic = 0; ic < 2; ic++) {
            const float* wp  = sW + (oc * 2 + ic) * 64;
            const float* inb = sIn + ic * 7056;
            #pragma unroll
            for (int ky = 0; ky < 8; ky++) {
                const float* r0 = inb + (oy * 4 + ky) * 84 + ox * 4;
                const float* r1 = r0 + 4 * 84;
                float v0[12], v1[12];
                #pragma unroll
                for (int j = 0; j < 12; j++) { v0[j] = r0[j]; v1[j] = r1[j]; }
                #pragma unroll
                for (int kx = 0; kx < 8; kx++) {
                    float ww = wp[ky * 8 + kx];
                    a00 += v0[kx] * ww;  a01 += v0[kx + 4] * ww;
                    a10 += v1[kx] * ww;  a11 += v1[kx + 4] * ww;
                }
            }
        }
        float bb = bias[oc];
        float* op = g_h1 + b * 12800 + oc * 400 + oy * 20 + ox;
        op[0]  = fmaxf(a00 + bb, 0.f); op[1]  = fmaxf(a01 + bb, 0.f);
        op[20] = fmaxf(a10 + bb, 0.f); op[21] = fmaxf(a11 + bb, 0.f);
    }
}

// ---------------- conv2: [B,32,20,20] k4 s2 -> [B,64,9,9], relu ----------------
__global__ __launch_bounds__(256) void k_conv2(const float* __restrict__ w,
                                               const float* __restrict__ bias) {
    extern __shared__ float sm[];
    float* sIn = sm;          // 12800
    float* sW  = sm + 12800;  // 16384
    int b = blockIdx.x, tid = threadIdx.x;
    const float* ip = g_h1 + b * 12800;
    for (int i = tid; i < 12800; i += 256) sIn[i] = ip[i];
    for (int ch = 0; ch < 2; ch++) {
        __syncthreads();
        for (int i = tid; i < 16384; i += 256) sW[i] = w[ch * 16384 + i];
        __syncthreads();
        if (tid < 216) {
            int ocg = tid / 27; int r = tid % 27; int oy = r / 3; int oxg = (r % 3) * 3;
            float acc[4][3] = {};
            int iy0 = oy * 2, ix0 = oxg * 2;
            for (int ic = 0; ic < 32; ic++) {
                #pragma unroll
                for (int ky = 0; ky < 4; ky++) {
                    const float* rp = sIn + ic * 400 + (iy0 + ky) * 20 + ix0;
                    float v[8];
                    #pragma unroll
                    for (int j = 0; j < 8; j++) v[j] = rp[j];
                    #pragma unroll
                    for (int u = 0; u < 4; u++) {
                        const float* wp = sW + ((ocg * 4 + u) * 32 + ic) * 16 + ky * 4;
                        #pragma unroll
                        for (int kx = 0; kx < 4; kx++) {
                            float ww = wp[kx];
                            acc[u][0] += v[kx] * ww;
                            acc[u][1] += v[kx + 2] * ww;
                            acc[u][2] += v[kx + 4] * ww;
                        }
                    }
                }
            }
            #pragma unroll
            for (int u = 0; u < 4; u++) {
                int oc = ch * 32 + ocg * 4 + u;
                float bb = bias[oc];
                float* op = g_h2 + b * 5184 + oc * 81 + oy * 9 + oxg;
                #pragma unroll
                for (int j = 0; j < 3; j++) op[j] = fmaxf(acc[u][j] + bb, 0.f);
            }
        }
    }
}

// ---------------- conv3: [B,64,9,9] k3 s1 -> [B,64,7,7], relu ----------------
__global__ __launch_bounds__(256) void k_conv3(const float* __restrict__ w,
                                               const float* __restrict__ bias) {
    extern __shared__ float sm[];
    float* sIn = sm;         // 5184
    float* sW  = sm + 5184;  // 36864
    int b = blockIdx.x, tid = threadIdx.x;
    const float* ip = g_h2 + b * 5184;
    for (int i = tid; i < 5184;  i += 256) sIn[i] = ip[i];
    for (int i = tid; i < 36864; i += 256) sW[i]  = w[i];
    __syncthreads();
    for (int it = tid; it < 448; it += 256) {
        int oc = it / 7, oy = it % 7;
        float acc[7] = {};
        for (int ic = 0; ic < 64; ic++) {
            const float* wp = sW + (oc * 64 + ic) * 9;
            #pragma unroll
            for (int ky = 0; ky < 3; ky++) {
                const float* rp = sIn + ic * 81 + (oy + ky) * 9;
                float v[9];
                #pragma unroll
                for (int j = 0; j < 9; j++) v[j] = rp[j];
                #pragma unroll
                for (int kx = 0; kx < 3; kx++) {
                    float ww = wp[ky * 3 + kx];
                    #pragma unroll
                    for (int j = 0; j < 7; j++) acc[j] += v[j + kx] * ww;
                }
            }
        }
        float bb = bias[oc];
        float* op = g_h3 + b * 3136 + oc * 49 + oy * 7;
        #pragma unroll
        for (int j = 0; j < 7; j++) op[j] = fmaxf(acc[j] + bb, 0.f);
    }
}

// ---------------- GEMM v2 ----------------
#define GBM 128
#define GBN 64
#define GBK 16
__global__ __launch_bounds__(256) void k_gemm2(const float* __restrict__ A,
                                               const float* __restrict__ W,
                                               const float* __restrict__ bias,
                                               float* __restrict__ C,
                                               int M, int N, int K, int Kc, int relu) {
    __shared__ float As[GBK][GBM];
    __shared__ float Ws[GBK][GBN];
    int bm = blockIdx.y * GBM, bn = blockIdx.x * GBN;
    int ks = blockIdx.z * Kc;
    int ke = min(ks + Kc, K);
    int tid = threadIdx.x;
    float acc[8][4];
    #pragma unroll
    for (int i = 0; i < 8; i++)
        #pragma unroll
        for (int j = 0; j < 4; j++) acc[i][j] = 0.f;

    int tm = (tid / 16) * 8, tn = (tid % 16) * 4;

    for (int k0 = ks; k0 < ke; k0 += GBK) {
        #pragma unroll
        for (int l = tid; l < 512; l += 256) {
            int m = l >> 2, kq = (l & 3) << 2;
            float4 v = *(const float4*)(A + (size_t)(bm + m) * K + k0 + kq);
            As[kq + 0][m] = v.x; As[kq + 1][m] = v.y;
            As[kq + 2][m] = v.z; As[kq + 3][m] = v.w;
        }
        {
            int n = tid >> 2, kq = (tid & 3) << 2;
            int gn = bn + n;
            float4 v = make_float4(0.f, 0.f, 0.f, 0.f);
            if (gn < N) v = *(const float4*)(W + (size_t)gn * K + k0 + kq);
            Ws[kq + 0][n] = v.x; Ws[kq + 1][n] = v.y;
            Ws[kq + 2][n] = v.z; Ws[kq + 3][n] = v.w;
        }
        __syncthreads();
        #pragma unroll
        for (int k = 0; k < GBK; k++) {
            float4 a0 = *(const float4*)&As[k][tm];
            float4 a1 = *(const float4*)&As[k][tm + 4];
            float4 bv = *(const float4*)&Ws[k][tn];
            float a[8] = {a0.x, a0.y, a0.z, a0.w, a1.x, a1.y, a1.z, a1.w};
            float bb[4] = {bv.x, bv.y, bv.z, bv.w};
            #pragma unroll
            for (int i = 0; i < 8; i++)
                #pragma unroll
                for (int j = 0; j < 4; j++) acc[i][j] += a[i] * bb[j];
        }
        __syncthreads();
    }

    if (Kc >= K) {
        #pragma unroll
        for (int i = 0; i < 8; i++) {
            int gm = bm + tm + i;
            #pragma unroll
            for (int j = 0; j < 4; j++) {
                int gn = bn + tn + j;
                if (gn < N) {
                    float v = acc[i][j] + bias[gn];
                    if (relu) v = fmaxf(v, 0.f);
                    C[(size_t)gm * N + gn] = v;
                }
            }
        }
    } else {
        float* Cp = C + (size_t)blockIdx.z * M * N;
        #pragma unroll
        for (int i = 0; i < 8; i++) {
            int gm = bm + tm + i;
            #pragma unroll
            for (int j = 0; j < 4; j++) {
                int gn = bn + tn + j;
                if (gn < N) Cp[(size_t)gm * N + gn] = acc[i][j];
            }
        }
    }
}

// ---------------- fc reduce ----------------
__global__ __launch_bounds__(256) void k_fcreduce(const float* __restrict__ fcb) {
    int i = blockIdx.x * 256 + threadIdx.x;
    if (i >= Bsz * EMB) return;
    int n = i & (EMB - 1);
    float s = fcb[n];
    #pragma unroll
    for (int p = 0; p < 7; p++) s += g_fcpart[p * Bsz * EMB + i];
    g_x[i] = fmaxf(s, 0.f);
}

// ---------------- heads ----------------
__global__ __launch_bounds__(64) void k_heads(const float* __restrict__ otw,
                                              const float* __restrict__ otb,
                                              const float* __restrict__ ctw,
                                              const float* __restrict__ ctb) {
    __shared__ float sx[EMB];
    int b = blockIdx.x, tid = threadIdx.x;
    for (int i = tid; i < EMB; i += 64) sx[i] = g_x[b * EMB + i];
    __syncthreads();
    if (tid < 42) {
        const float* wp = (tid < 40) ? (otw + tid * EMB) : (ctw + (tid - 40) * EMB);
        float s = (tid < 40) ? otb[tid] : ctb[tid - 40];
        for (int k = 0; k < EMB; k++) s += sx[k] * wp[k];
        if (tid < 40) g_ot[b * 40 + tid] = s;
        else          g_ct[b * 2 + (tid - 40)] = s;
    }
}

// ---------------- fused upsample + residual 3x3 conv via 3-term tf32 mma ----------------
// smem: sIn (fp32, 14*R), sWh (w_hi fragments, 5184), sAux (raw rows in phase 0/1,
// then w_lo fragments in phase 2; size auxF = max(24*PP, 5184)), sB (24).
#define UC_THREADS 224
__global__ __launch_bounds__(UC_THREADS) void k_upconv_mma(
        const float* __restrict__ src, const float* __restrict__ w,
        const float* __restrict__ bias, float* __restrict__ out,
        int inS, int S, int W_s, int R, int PP, int auxF,
        float scale, int npx, int npatch) {
    extern __shared__ float sm[];
    float* sIn  = sm;                    // 14*R fp32
    float* sWh  = sm + 14 * R;           // 5184 (w_hi)
    float* sAux = sWh + 5184;            // auxF: raw rows, later w_lo
    float* sB   = sAux + auxF;           // 24
    int tid = threadIdx.x;
    int lane = tid & 31, wid = tid >> 5;
    int b = blockIdx.y, ty = blockIdx.x;
    int y0 = ty * 12;

    // --- phase 0: stage raw source rows (coalesced) + w_hi fragments + bias
    int sy0 = (int)(fmaxf((float)(y0 - 1), 0.f) * scale);
    const float* srcb = src + (size_t)b * 24 * inS * inS;
    int rawTot = 24 * 9 * inS;
    for (int e = tid; e < rawTot; e += UC_THREADS) {
        int ic = e / (9 * inS);
        int r2 = e % (9 * inS);
        int ry = r2 / inS, x = r2 % inS;
        int sy = sy0 + ry;
        float v = (sy < inS) ? srcb[(size_t)ic * inS * inS + sy * inS + x] : 0.f;
        sAux[ic * PP + ry * inS + x] = v;
    }
    for (int idx = tid; idx < 5184; idx += UC_THREADS) {
        int combo = idx >> 6;            // (tap*3+ks)*3+nt
        int lr = idx & 63;
        int l = lr >> 1, j = lr & 1;
        int tap = combo / 9;
        int ks  = (combo % 9) / 3;
        int nt  = combo % 3;
        int oc = nt * 8 + (l >> 2);
        int ic = ks * 8 + (l & 3) + 4 * j;
        sWh[idx] = __uint_as_float(cvt_tf32(w[(oc * 24 + ic) * 9 + tap]));
    }
    if (tid < 24) sB[tid] = bias[tid];
    __syncthreads();

    // --- phase 1: bilinear upsample into conv tile (fp32), linear STS
    int tileTot = 14 * W_s * 24;
    int rowE = W_s * 24;
    for (int e = tid; e < tileTot; e += UC_THREADS) {
        int rr = e / rowE;
        int r2 = e % rowE;
        int cc = r2 / 24, ic = r2 % 24;
        int gy = y0 + rr - 1, gx = cc - 1;
        float v = 0.f;
        if (gy >= 0 && gy < S && gx >= 0 && gx < S) {
            float py = gy * scale;
            int yl = min((int)py, inS - 2);
            float wy = py - (float)yl;
            float px = gx * scale;
            int xl = min((int)px, inS - 2);
            float wx = px - (float)xl;
            const float* rp = sAux + ic * PP + (yl - sy0) * inS + xl;
            float v00 = rp[0], v01 = rp[1], v10 = rp[inS], v11 = rp[inS + 1];
            v = (1.f - wy) * ((1.f - wx) * v00 + wx * v01) +
                wy * ((1.f - wx) * v10 + wx * v11);
        }
        sIn[rr * R + r2] = v;
    }
    __syncthreads();

    // --- phase 1.5: raw rows dead; overwrite sAux with w_lo fragments
    for (int idx = tid; idx < 5184; idx += UC_THREADS) {
        int combo = idx >> 6;
        int lr = idx & 63;
        int l = lr >> 1, j = lr & 1;
        int tap = combo / 9;
        int ks  = (combo % 9) / 3;
        int nt  = combo % 3;
        int oc = nt * 8 + (l >> 2);
        int ic = ks * 8 + (l & 3) + 4 * j;
        float wv = w[(oc * 24 + ic) * 9 + tap];
        float hi = __uint_as_float(cvt_tf32(wv));
        sAux[idx] = __uint_as_float(cvt_tf32(wv - hi));
    }
    __syncthreads();
    const float* sWl = sAux;

    // --- phase 2: 3-term tf32 mma over patches
    int g = lane >> 2, tg = lane & 3;
    int labase = (g >> 2) * R + (g & 3) * 24 + tg;
    float* ob = out + (size_t)b * 24 * S * S;

    for (int p = wid; p < npatch; p += 7) {
        int pr = p / npx, pc = p % npx;
        int prow4 = pr * 4, pcol4 = pc * 4;
        if (y0 + prow4 >= S) continue;
        float c0[4] = {0.f, 0.f, 0.f, 0.f};
        float c1[4] = {0.f, 0.f, 0.f, 0.f};
        float c2[4] = {0.f, 0.f, 0.f, 0.f};
        int pbase = prow4 * R + pcol4 * 24 + labase;
        #pragma unroll
        for (int ky = 0; ky < 3; ky++) {
            #pragma unroll
            for (int kx = 0; kx < 3; kx++) {
                int tap = ky * 3 + kx;
                int abase = pbase + ky * R + kx * 24;
                #pragma unroll
                for (int ks = 0; ks < 3; ks++) {
                    int ao = abase + ks * 8;
                    float af0 = sIn[ao];
                    float af1 = sIn[ao + 2 * R];
                    float af2 = sIn[ao + 4];
                    float af3 = sIn[ao + 2 * R + 4];
                    uint32_t ah[4], al[4];
                    ah[0] = cvt_tf32(af0); al[0] = cvt_tf32(af0 - __uint_as_float(ah[0]));
                    ah[1] = cvt_tf32(af1); al[1] = cvt_tf32(af1 - __uint_as_float(ah[1]));
                    ah[2] = cvt_tf32(af2); al[2] = cvt_tf32(af2 - __uint_as_float(ah[2]));
                    ah[3] = cvt_tf32(af3); al[3] = cvt_tf32(af3 - __uint_as_float(ah[3]));
                    int fo = (tap * 3 + ks) * 192;  // 3 nt * 64 floats
                    const float2* wfh = (const float2*)(sWh + fo);
                    const float2* wfl = (const float2*)(sWl + fo);
                    float2 bh0 = wfh[lane],      bl0 = wfl[lane];
                    float2 bh1 = wfh[32 + lane], bl1 = wfl[32 + lane];
                    float2 bh2 = wfh[64 + lane], bl2 = wfl[64 + lane];
                    mma_tf32(c0, ah, __float_as_uint(bh0.x), __float_as_uint(bh0.y));
                    mma_tf32(c0, al, __float_as_uint(bh0.x), __float_as_uint(bh0.y));
                    mma_tf32(c0, ah, __float_as_uint(bl0.x), __float_as_uint(bl0.y));
                    mma_tf32(c1, ah, __float_as_uint(bh1.x), __float_as_uint(bh1.y));
                    mma_tf32(c1, al, __float_as_uint(bh1.x), __float_as_uint(bh1.y));
                    mma_tf32(c1, ah, __float_as_uint(bl1.x), __float_as_uint(bl1.y));
                    mma_tf32(c2, ah, __float_as_uint(bh2.x), __float_as_uint(bh2.y));
                    mma_tf32(c2, al, __float_as_uint(bh2.x), __float_as_uint(bh2.y));
                    mma_tf32(c2, ah, __float_as_uint(bl2.x), __float_as_uint(bl2.y));
                }
            }
        }
        // epilogue: residual (fp32, unrounded) + bias + relu, masked stores
        int gy = y0 + prow4 + (g >> 2);
        int gx = pcol4 + (g & 3);
        int rrc = prow4 + (g >> 2) + 1;
        int ccc = pcol4 + (g & 3) + 1;
        const float* rcen = sIn + rrc * R + ccc * 24;
        bool v0 = (gy < S) && (gx < S);
        bool v1 = (gy + 2 < S) && (gx < S);
        #pragma unroll
        for (int nt = 0; nt < 3; nt++) {
            float* cp = (nt == 0) ? c0 : (nt == 1) ? c1 : c2;
            int oc = nt * 8 + tg * 2;
            float bs0 = sB[oc], bs1 = sB[oc + 1];
            if (v0) {
                ob[((size_t)oc * S + gy) * S + gx] =
                    fmaxf(cp[0] + rcen[oc] + bs0, 0.f);
                ob[((size_t)(oc + 1) * S + gy) * S + gx] =
                    fmaxf(cp[1] + rcen[oc + 1] + bs1, 0.f);
            }
            if (v1) {
                const float* rc2 = rcen + 2 * R;
                ob[((size_t)oc * S + gy + 2) * S + gx] =
                    fmaxf(cp[2] + rc2[oc] + bs0, 0.f);
                ob[((size_t)(oc + 1) * S + gy + 2) * S + gx] =
                    fmaxf(cp[3] + rc2[oc + 1] + bs1, 0.f);
            }
        }
    }
}

// ---------------- fused epilogue: 1x1 conv + sigmoid + flow + ct + grid + warp ----------------
__global__ __launch_bounds__(256) void k_final(const float* __restrict__ inp,
                                               const float* __restrict__ c3w,
                                               const float* __restrict__ c3b,
                                               float* __restrict__ outp) {
    __shared__ float s_w[KOBJ * 24];
    __shared__ float s_b[KOBJ];
    __shared__ float s_ot[KOBJ * 2];
    __shared__ float s_ct[2];
    int b = blockIdx.y, tid = threadIdx.x;
    int p = blockIdx.x * 256 + tid;
    for (int i = tid; i < KOBJ * 24; i += 256) s_w[i] = c3w[i];
    if (tid < KOBJ) s_b[tid] = c3b[tid];
    if (tid < KOBJ * 2) s_ot[tid] = g_ot[b * 40 + tid];
    if (tid < 2) s_ct[tid] = g_ct[b * 2 + tid];
    __syncthreads();
    if (p >= 7056) return;
    const float* mp = g_m84b + (size_t)b * 24 * 7056 + p;
    float mv[24];
    #pragma unroll
    for (int c = 0; c < 24; c++) mv[c] = mp[c * 7056];
    float fy = s_ct[0], fx = s_ct[1];
    #pragma unroll 4
    for (int k = 0; k < KOBJ; k++) {
        float s = s_b[k];
        #pragma unroll
        for (int c = 0; c < 24; c++) s += mv[c] * s_w[k * 24 + c];
        float mask = 1.f / (1.f + __expf(-s));
        fy += mask * s_ot[k * 2];
        fx += mask * s_ot[k * 2 + 1];
    }
    int gy = p / 84, gx = p % 84;
    const float isf = 0.01f * 84.0f;
    float ys = isf * fy + (float)gy;
    float xs = isf * fx + (float)gx;
    const float* src = inp + (size_t)b * 14112 + 7056;  // frame 1
    int x0 = min(max((int)floorf(xs), 0), 83);
    int y0 = min(max((int)floorf(ys), 0), 83);
    int x1 = min(x0 + 1, 83);
    int y1 = min(y0 + 1, 83);
    float Ia = src[y0 * 84 + x0], Ib = src[y1 * 84 + x0];
    float Ic = src[y0 * 84 + x1], Id = src[y1 * 84 + x1];
    float xc = fminf(fmaxf(xs, 0.f), 83.f);
    float yc = fminf(fmaxf(ys, 0.f), 83.f);
    float x0f = (float)x0, x1f = (float)x1, y0f = (float)y0, y1f = (float)y1;
    float o = (x1f - xc) * (y1f - yc) * Ia + (x1f - xc) * (yc - y0f) * Ib +
              (xc - x0f) * (y1f - yc) * Ic + (xc - x0f) * (yc - y0f) * Id;
    outp[(size_t)b * 7056 + p] = o;
}

// ---------------- launch ----------------
extern "C" void kernel_launch(void* const* d_in, const int* in_sizes, int n_in,
                              void* d_out, int out_size) {
    const float* inp = (const float*)d_in[0];
    const float* cw1 = (const float*)d_in[1];
    const float* cb1 = (const float*)d_in[2];
    const float* cw2 = (const float*)d_in[3];
    const float* cb2 = (const float*)d_in[4];
    const float* cw3 = (const float*)d_in[5];
    const float* cb3 = (const float*)d_in[6];
    const float* fcw = (const float*)d_in[7];
    const float* fcb = (const float*)d_in[8];
    const float* otw = (const float*)d_in[9];
    const float* otb = (const float*)d_in[10];
    const float* ctw = (const float*)d_in[11];
    const float* ctb = (const float*)d_in[12];
    const float* m1w = (const float*)d_in[13];
    const float* m1b = (const float*)d_in[14];
    const float* c1w = (const float*)d_in[15];
    const float* c1b = (const float*)d_in[16];
    const float* c2w = (const float*)d_in[17];
    const float* c2b = (const float*)d_in[18];
    const float* c3w = (const float*)d_in[19];
    const float* c3b = (const float*)d_in[20];
    float* outp = (float*)d_out;

    cudaFuncSetAttribute(k_conv1,  cudaFuncAttributeMaxDynamicSharedMemorySize, 72832);
    cudaFuncSetAttribute(k_conv2,  cudaFuncAttributeMaxDynamicSharedMemorySize, 116736);
    cudaFuncSetAttribute(k_conv3,  cudaFuncAttributeMaxDynamicSharedMemorySize, 168192);
    cudaFuncSetAttribute(k_upconv_mma, cudaFuncAttributeMaxDynamicSharedMemorySize, 173120);

    float *p_h3, *p_x, *p_fcpart, *p_m21, *p_m42b, *p_m84b;
    cudaGetSymbolAddress((void**)&p_h3,     g_h3);
    cudaGetSymbolAddress((void**)&p_x,      g_x);
    cudaGetSymbolAddress((void**)&p_fcpart, g_fcpart);
    cudaGetSymbolAddress((void**)&p_m21,    g_m21);
    cudaGetSymbolAddress((void**)&p_m42b,   g_m42b);
    cudaGetSymbolAddress((void**)&p_m84b,   g_m84b);

    // encoder
    k_conv1<<<Bsz, 256, 72832>>>(inp, cw1, cb1);
    k_conv2<<<Bsz, 256, 116736>>>(cw2, cb2);
    k_conv3<<<Bsz, 256, 168192>>>(cw3, cb3);
    // fc: split-K=7 + reduce(relu)
    k_gemm2<<<dim3(EMB / GBN, Bsz / GBM, 7), 256>>>(p_h3, fcw, fcb, p_fcpart,
                                                    Bsz, EMB, 3136, 448, 0);
    k_fcreduce<<<(Bsz * EMB + 255) / 256, 256>>>(fcb);
    // mask fc
    k_gemm2<<<dim3((10584 + GBN - 1) / GBN, Bsz / GBM, 1), 256>>>(p_x, m1w, m1b, p_m21,
                                                                  Bsz, 10584, EMB, EMB, 0);
    // heads
    k_heads<<<Bsz, 64>>>(otw, otb, ctw, ctb);
    // decoder: fused upsample + residual conv via 3-term tf32 mma
    // conv42: inS=21,S=42,W_s=46,R=1108,PP=191,auxF=5184
    //   smem = (14*1108 + 5184 + 5184 + 24)*4 = 103,616 B (2 blocks/SM)
    k_upconv_mma<<<dim3(4, Bsz), UC_THREADS, 103616>>>(p_m21, c1w, c1b, p_m42b,
                                                       21, 42, 46, 1108, 191, 5184,
                                                       20.f / 41.f, 11, 33);
    // conv84: inS=42,S=84,W_s=86,R=2068,PP=380,auxF=9120
    //   smem = (14*2068 + 5184 + 9120 + 24)*4 = 173,120 B (1 block/SM)
    k_upconv_mma<<<dim3(7, Bsz), UC_THREADS, 173120>>>(p_m42b, c2w, c2b, p_m84b,
                                                       42, 84, 86, 2068, 380, 9120,
                                                       41.f / 83.f, 21, 63);
    // fused: 1x1 conv + sigmoid masks + flow + warp
    k_final<<<dim3(28, Bsz), 256>>>(inp, c3w, c3b, outp);
    (void)in_sizes; (void)n_in; (void)out_size;
}

// round 9
// speedup vs baseline: 1.0071x; 1.0071x over previous
#include <cuda_runtime.h>
#include <cuda_bf16.h>
#include <math.h>
#include <stdint.h>

#define Bsz 512
#define HH 84
#define WW 84
#define KOBJ 20
#define DEPTH 24
#define EMB 512

// ---------------- scratch (static device globals; no allocations) ----------------
__device__ float g_h1[Bsz * 32 * 20 * 20];
__device__ float g_h3[Bsz * 64 * 7 * 7];
__device__ float g_fcpart[7 * Bsz * EMB];
__device__ float g_x [Bsz * EMB];
__device__ float g_ot[Bsz * KOBJ * 2];
__device__ float g_ct[Bsz * 2];
__device__ float g_m21 [Bsz * DEPTH * 21 * 21];
__device__ float g_m42b[Bsz * DEPTH * 42 * 42];
__device__ float g_m84b[Bsz * DEPTH * 84 * 84];

// ---------------- helpers ----------------
__device__ __forceinline__ uint32_t pack_bf16x2(float lo, float hi) {
    uint32_t r;
    asm("cvt.rn.bf16x2.f32 %0, %1, %2;" : "=r"(r) : "f"(hi), "f"(lo));
    return r;  // low16 = bf16(lo), high16 = bf16(hi)
}
__device__ __forceinline__ void unpack_bf16x2(uint32_t u, float& lo, float& hi) {
    lo = __uint_as_float(u << 16);
    hi = __uint_as_float(u & 0xFFFF0000u);
}
__device__ __forceinline__ float bf16f(float v) {
    return __bfloat162float(__float2bfloat16(v));
}
__device__ __forceinline__ void mma_bf16(float c[4], const uint32_t a[4],
                                         uint32_t b0, uint32_t b1) {
    asm volatile("mma.sync.aligned.m16n8k16.row.col.f32.bf16.bf16.f32 "
        "{%0,%1,%2,%3}, {%4,%5,%6,%7}, {%8,%9}, {%0,%1,%2,%3};"
        : "+f"(c[0]), "+f"(c[1]), "+f"(c[2]), "+f"(c[3])
        : "r"(a[0]), "r"(a[1]), "r"(a[2]), "r"(a[3]), "r"(b0), "r"(b1));
}

// ---------------- conv1: [B,2,84,84] k8 s4 -> [B,32,20,20], relu ----------------
__global__ __launch_bounds__(256) void k_conv1(const float* __restrict__ inp,
                                               const float* __restrict__ w,
                                               const float* __restrict__ bias) {
    extern __shared__ float sm[];
    float* sIn = sm;          // 14112
    float* sW  = sm + 14112;  // 4096
    int b = blockIdx.x, tid = threadIdx.x;
    const float* ip = inp + b * 14112;
    for (int i = tid; i < 14112; i += 256) sIn[i] = ip[i];
    for (int i = tid; i < 4096;  i += 256) sW[i]  = w[i];
    __syncthreads();
    for (int o = tid; o < 3200; o += 256) {
        int oc = o / 100; int r = o % 100;
        int oy = (r / 10) * 2, ox = (r % 10) * 2;
        float a00 = 0.f, a01 = 0.f, a10 = 0.f, a11 = 0.f;
        for (int ic = 0; ic < 2; ic++) {
            const float* wp  = sW + (oc * 2 + ic) * 64;
            const float* inb = sIn + ic * 7056;
            #pragma unroll
            for (int ky = 0; ky < 8; ky++) {
                const float* r0 = inb + (oy * 4 + ky) * 84 + ox * 4;
                const float* r1 = r0 + 4 * 84;
                float v0[12], v1[12];
                #pragma unroll
                for (int j = 0; j < 12; j++) { v0[j] = r0[j]; v1[j] = r1[j]; }
                #pragma unroll
                for (int kx = 0; kx < 8; kx++) {
                    float ww = wp[ky * 8 + kx];
                    a00 += v0[kx] * ww;  a01 += v0[kx + 4] * ww;
                    a10 += v1[kx] * ww;  a11 += v1[kx + 4] * ww;
                }
            }
        }
        float bb = bias[oc];
        float* op = g_h1 + b * 12800 + oc * 400 + oy * 20 + ox;
        op[0]  = fmaxf(a00 + bb, 0.f); op[1]  = fmaxf(a01 + bb, 0.f);
        op[20] = fmaxf(a10 + bb, 0.f); op[21] = fmaxf(a11 + bb, 0.f);
    }
}

// ---------------- conv2+conv3 fused (h2 stays in smem) ----------------
// smem (42048 floats = 168192 B):
//   phase A: in1 [0,12800) | w2 chunk [12800,29184) | h2 [36864,42048)
//   phase B: w3 [0,36864)  | h2 (as conv3 input)    [36864,42048)
__global__ __launch_bounds__(256) void k_conv23(const float* __restrict__ w2,
                                                const float* __restrict__ b2,
                                                const float* __restrict__ w3,
                                                const float* __restrict__ b3) {
    extern __shared__ float sm[];
    float* sIn1 = sm;
    float* sW2  = sm + 12800;
    float* sH2  = sm + 36864;
    int b = blockIdx.x, tid = threadIdx.x;
    const float* ip = g_h1 + b * 12800;
    for (int i = tid; i < 12800; i += 256) sIn1[i] = ip[i];
    for (int ch = 0; ch < 2; ch++) {
        __syncthreads();
        for (int i = tid; i < 16384; i += 256) sW2[i] = w2[ch * 16384 + i];
        __syncthreads();
        if (tid < 216) {
            int ocg = tid / 27; int r = tid % 27; int oy = r / 3; int oxg = (r % 3) * 3;
            float acc[4][3] = {};
            int iy0 = oy * 2, ix0 = oxg * 2;
            for (int ic = 0; ic < 32; ic++) {
                #pragma unroll
                for (int ky = 0; ky < 4; ky++) {
                    const float* rp = sIn1 + ic * 400 + (iy0 + ky) * 20 + ix0;
                    float v[8];
                    #pragma unroll
                    for (int j = 0; j < 8; j++) v[j] = rp[j];
                    #pragma unroll
                    for (int u = 0; u < 4; u++) {
                        const float* wp = sW2 + ((ocg * 4 + u) * 32 + ic) * 16 + ky * 4;
                        #pragma unroll
                        for (int kx = 0; kx < 4; kx++) {
                            float ww = wp[kx];
                            acc[u][0] += v[kx] * ww;
                            acc[u][1] += v[kx + 2] * ww;
                            acc[u][2] += v[kx + 4] * ww;
                        }
                    }
                }
            }
            #pragma unroll
            for (int u = 0; u < 4; u++) {
                int oc = ch * 32 + ocg * 4 + u;
                float bb = b2[oc];
                float* op = sH2 + oc * 81 + oy * 9 + oxg;
                #pragma unroll
                for (int j = 0; j < 3; j++) op[j] = fmaxf(acc[u][j] + bb, 0.f);
            }
        }
    }
    __syncthreads();
    // phase B: load w3 over in1/w2
    for (int i = tid; i < 36864; i += 256) sm[i] = w3[i];
    __syncthreads();
    for (int it = tid; it < 448; it += 256) {
        int oc = it / 7, oy = it % 7;
        float acc[7] = {};
        for (int ic = 0; ic < 64; ic++) {
            const float* wp = sm + (oc * 64 + ic) * 9;
            #pragma unroll
            for (int ky = 0; ky < 3; ky++) {
                const float* rp = sH2 + ic * 81 + (oy + ky) * 9;
                float v[9];
                #pragma unroll
                for (int j = 0; j < 9; j++) v[j] = rp[j];
                #pragma unroll
                for (int kx = 0; kx < 3; kx++) {
                    float ww = wp[ky * 3 + kx];
                    #pragma unroll
                    for (int j = 0; j < 7; j++) acc[j] += v[j + kx] * ww;
                }
            }
        }
        float bb = b3[oc];
        float* op = g_h3 + b * 3136 + oc * 49 + oy * 7;
        #pragma unroll
        for (int j = 0; j < 7; j++) op[j] = fmaxf(acc[j] + bb, 0.f);
    }
}

// ---------------- GEMM v2 ----------------
#define GBM 128
#define GBN 64
#define GBK 16
__global__ __launch_bounds__(256) void k_gemm2(const float* __restrict__ A,
                                               const float* __restrict__ W,
                                               const float* __restrict__ bias,
                                               float* __restrict__ C,
                                               int M, int N, int K, int Kc, int relu) {
    __shared__ float As[GBK][GBM];
    __shared__ float Ws[GBK][GBN];
    int bm = blockIdx.y * GBM, bn = blockIdx.x * GBN;
    int ks = blockIdx.z * Kc;
    int ke = min(ks + Kc, K);
    int tid = threadIdx.x;
    float acc[8][4];
    #pragma unroll
    for (int i = 0; i < 8; i++)
        #pragma unroll
        for (int j = 0; j < 4; j++) acc[i][j] = 0.f;

    int tm = (tid / 16) * 8, tn = (tid % 16) * 4;

    for (int k0 = ks; k0 < ke; k0 += GBK) {
        #pragma unroll
        for (int l = tid; l < 512; l += 256) {
            int m = l >> 2, kq = (l & 3) << 2;
            float4 v = *(const float4*)(A + (size_t)(bm + m) * K + k0 + kq);
            As[kq + 0][m] = v.x; As[kq + 1][m] = v.y;
            As[kq + 2][m] = v.z; As[kq + 3][m] = v.w;
        }
        {
            int n = tid >> 2, kq = (tid & 3) << 2;
            int gn = bn + n;
            float4 v = make_float4(0.f, 0.f, 0.f, 0.f);
            if (gn < N) v = *(const float4*)(W + (size_t)gn * K + k0 + kq);
            Ws[kq + 0][n] = v.x; Ws[kq + 1][n] = v.y;
            Ws[kq + 2][n] = v.z; Ws[kq + 3][n] = v.w;
        }
        __syncthreads();
        #pragma unroll
        for (int k = 0; k < GBK; k++) {
            float4 a0 = *(const float4*)&As[k][tm];
            float4 a1 = *(const float4*)&As[k][tm + 4];
            float4 bv = *(const float4*)&Ws[k][tn];
            float a[8] = {a0.x, a0.y, a0.z, a0.w, a1.x, a1.y, a1.z, a1.w};
            float bb[4] = {bv.x, bv.y, bv.z, bv.w};
            #pragma unroll
            for (int i = 0; i < 8; i++)
                #pragma unroll
                for (int j = 0; j < 4; j++) acc[i][j] += a[i] * bb[j];
        }
        __syncthreads();
    }

    if (Kc >= K) {
        #pragma unroll
        for (int i = 0; i < 8; i++) {
            int gm = bm + tm + i;
            #pragma unroll
            for (int j = 0; j < 4; j++) {
                int gn = bn + tn + j;
                if (gn < N) {
                    float v = acc[i][j] + bias[gn];
                    if (relu) v = fmaxf(v, 0.f);
                    C[(size_t)gm * N + gn] = v;
                }
            }
        }
    } else {
        float* Cp = C + (size_t)blockIdx.z * M * N;
        #pragma unroll
        for (int i = 0; i < 8; i++) {
            int gm = bm + tm + i;
            #pragma unroll
            for (int j = 0; j < 4; j++) {
                int gn = bn + tn + j;
                if (gn < N) Cp[(size_t)gm * N + gn] = acc[i][j];
            }
        }
    }
}

// ---------------- fc reduce + heads fused ----------------
__global__ __launch_bounds__(256) void k_fcredheads(const float* __restrict__ fcb,
                                                    const float* __restrict__ otw,
                                                    const float* __restrict__ otb,
                                                    const float* __restrict__ ctw,
                                                    const float* __restrict__ ctb) {
    __shared__ float sx[EMB];
    int b = blockIdx.x, tid = threadIdx.x;
    for (int i = tid; i < EMB; i += 256) {
        float s = fcb[i];
        #pragma unroll
        for (int p = 0; p < 7; p++) s += g_fcpart[p * Bsz * EMB + b * EMB + i];
        float v = fmaxf(s, 0.f);
        g_x[b * EMB + i] = v;
        sx[i] = v;
    }
    __syncthreads();
    if (tid < 42) {
        const float* wp = (tid < 40) ? (otw + tid * EMB) : (ctw + (tid - 40) * EMB);
        float s = (tid < 40) ? otb[tid] : ctb[tid - 40];
        for (int k = 0; k < EMB; k++) s += sx[k] * wp[k];
        if (tid < 40) g_ot[b * 40 + tid] = s;
        else          g_ct[b * 2 + (tid - 40)] = s;
    }
}

// ======= fused upsample + residual 3x3 conv via bf16 m16n8k16 HMMA, 3-term ========
// Block = 1 batch x band of 4 output rows. Patch = 4x4 pixels (M=16), N=24 oc,
// K per tap padded to 32 (2 k16-steps), 9 taps, 3 compensation terms.
// smem: fp32 tile [6][Wp][28] (ic-last, pad 28, pads zeroed), B fragments 6912 u32
// (fragment-ordered, hi+lo; region shared with raw src staging), bias[24].
__global__ __launch_bounds__(256) void k_upconv_hmma(
        const float* __restrict__ src, const float* __restrict__ w,
        const float* __restrict__ bias, float* __restrict__ out,
        int inS, int S, int Wp, int npx, float scale, int tileF) {
    extern __shared__ float sm[];
    float* sTile = sm;                          // tileF = 6*Wp*28
    uint32_t* sBfr = (uint32_t*)(sm + tileF);   // 6912 u32 (alias: raw staging)
    float* sRaw = sm + tileF;
    float* sBias = sm + tileF + 6912;
    int tid = threadIdx.x, lane = tid & 31, wid = tid >> 5;
    int b = blockIdx.y, band = blockIdx.x;
    int y0 = band * 4;
    int W28 = Wp * 28;

    // phase 0: stage 6 raw source rows + bias
    int sy0 = (int)(fmaxf((float)(y0 - 1), 0.f) * scale);
    const float* srcb = src + (size_t)b * 24 * inS * inS;
    int rawTot = 24 * 6 * inS;
    for (int e = tid; e < rawTot; e += 256) {
        int ic = e / (6 * inS);
        int r2 = e % (6 * inS);
        int ry = r2 / inS, x = r2 % inS;
        int sy = sy0 + ry;
        sRaw[e] = (sy < inS) ? srcb[(size_t)ic * inS * inS + sy * inS + x] : 0.f;
    }
    if (tid < 24) sBias[tid] = bias[tid];
    __syncthreads();

    // phase 1: bilinear upsample -> fp32 tile (zero borders + ic pad)
    int tileTot = 6 * W28;
    for (int e = tid; e < tileTot; e += 256) {
        int ic = e % 28;
        int t = e / 28;
        int c = t % Wp, r = t / Wp;
        int gy = y0 + r - 1, gx = c - 1;
        float v = 0.f;
        if (ic < 24 && gy >= 0 && gy < S && gx >= 0 && gx < S) {
            float py = gy * scale;
            int yl = min((int)py, inS - 2);
            float wy = py - (float)yl;
            float px = gx * scale;
            int xl = min((int)px, inS - 2);
            float wx = px - (float)xl;
            const float* rp = sRaw + ic * (6 * inS) + (yl - sy0) * inS + xl;
            float v00 = rp[0], v01 = rp[1], v10 = rp[inS], v11 = rp[inS + 1];
            v = (1.f - wy) * ((1.f - wx) * v00 + wx * v01) +
                wy * ((1.f - wx) * v10 + wx * v11);
        }
        sTile[e] = v;
    }
    __syncthreads();

    // phase 2: build B fragments (hi & lo), overwriting raw staging
    // layout u32: [tap][ks][hl][nt][lane][r]  (e is exactly that linear index)
    for (int e = tid; e < 6912; e += 256) {
        int tap = e / 768;
        int rm = e % 768;
        int ks = rm / 384; rm %= 384;
        int hl = rm / 192; rm %= 192;
        int nt = rm / 64;
        int l2 = rm % 64;
        int ln = l2 >> 1, r = l2 & 1;
        int g = ln >> 2, tg = ln & 3;
        int oc = nt * 8 + g;
        int ic0 = ks * 16 + 2 * tg + r * 8;
        float v0 = 0.f, v1 = 0.f;
        if (ic0 < 24) {
            float wv = w[(oc * 24 + ic0) * 9 + tap];
            float h = bf16f(wv);
            v0 = (hl == 0) ? h : (wv - h);
        }
        if (ic0 + 1 < 24) {
            float wv = w[(oc * 24 + ic0 + 1) * 9 + tap];
            float h = bf16f(wv);
            v1 = (hl == 0) ? h : (wv - h);
        }
        sBfr[e] = pack_bf16x2(v0, v1);
    }
    __syncthreads();

    // phase 3: per-warp patch loop
    int g = lane >> 2, tg = lane & 3;
    float* ob = out + (size_t)b * 24 * S * S;
    for (int p = wid; p < npx; p += 8) {
        int pcol4 = p * 4;
        int colbase = pcol4 + (g & 3);
        float c0[4] = {0.f, 0.f, 0.f, 0.f};
        float c1[4] = {0.f, 0.f, 0.f, 0.f};
        float c2[4] = {0.f, 0.f, 0.f, 0.f};
        #pragma unroll
        for (int ky = 0; ky < 3; ky++) {
            #pragma unroll
            for (int kx = 0; kx < 3; kx++) {
                int tap = ky * 3 + kx;
                int rb = ((g >> 2) + ky) * W28 + (colbase + kx) * 28;
                #pragma unroll
                for (int ks = 0; ks < 2; ks++) {
                    int ab = rb + ks * 16 + 2 * tg;
                    float2 p0 = *(const float2*)(sTile + ab);
                    float2 p1 = *(const float2*)(sTile + ab + 2 * W28);
                    float2 p2 = *(const float2*)(sTile + ab + 8);
                    float2 p3 = *(const float2*)(sTile + ab + 2 * W28 + 8);
                    uint32_t ah[4], al[4];
                    ah[0] = pack_bf16x2(p0.x, p0.y);
                    ah[1] = pack_bf16x2(p1.x, p1.y);
                    ah[2] = pack_bf16x2(p2.x, p2.y);
                    ah[3] = pack_bf16x2(p3.x, p3.y);
                    {
                        float h0, h1;
                        unpack_bf16x2(ah[0], h0, h1);
                        al[0] = pack_bf16x2(p0.x - h0, p0.y - h1);
                        unpack_bf16x2(ah[1], h0, h1);
                        al[1] = pack_bf16x2(p1.x - h0, p1.y - h1);
                        unpack_bf16x2(ah[2], h0, h1);
                        al[2] = pack_bf16x2(p2.x - h0, p2.y - h1);
                        unpack_bf16x2(ah[3], h0, h1);
                        al[3] = pack_bf16x2(p3.x - h0, p3.y - h1);
                    }
                    const uint2* bh = (const uint2*)(sBfr + (tap * 4 + ks * 2) * 192);
                    const uint2* bl = (const uint2*)(sBfr + (tap * 4 + ks * 2 + 1) * 192);
                    uint2 bh0 = bh[lane], bh1 = bh[32 + lane], bh2 = bh[64 + lane];
                    uint2 bl0 = bl[lane], bl1 = bl[32 + lane], bl2 = bl[64 + lane];
                    mma_bf16(c0, ah, bh0.x, bh0.y);
                    mma_bf16(c1, ah, bh1.x, bh1.y);
                    mma_bf16(c2, ah, bh2.x, bh2.y);
                    mma_bf16(c0, al, bh0.x, bh0.y);
                    mma_bf16(c1, al, bh1.x, bh1.y);
                    mma_bf16(c2, al, bh2.x, bh2.y);
                    mma_bf16(c0, ah, bl0.x, bl0.y);
                    mma_bf16(c1, ah, bl1.x, bl1.y);
                    mma_bf16(c2, ah, bl2.x, bl2.y);
                }
            }
        }
        // epilogue: fp32 residual + bias + relu, masked stores
        int gx = colbase;
        int pr = g >> 2;
        int gy0 = y0 + pr, gy1 = y0 + pr + 2;
        const float* rc0 = sTile + (pr + 1) * W28 + (gx + 1) * 28;
        const float* rc1 = rc0 + 2 * W28;
        bool v0 = (gy0 < S) && (gx < S);
        bool v1 = (gy1 < S) && (gx < S);
        #pragma unroll
        for (int nt = 0; nt < 3; nt++) {
            const float* cp = (nt == 0) ? c0 : (nt == 1) ? c1 : c2;
            int oc = nt * 8 + 2 * tg;
            if (v0) {
                ob[((size_t)oc * S + gy0) * S + gx] =
                    fmaxf(cp[0] + rc0[oc] + sBias[oc], 0.f);
                ob[((size_t)(oc + 1) * S + gy0) * S + gx] =
                    fmaxf(cp[1] + rc0[oc + 1] + sBias[oc + 1], 0.f);
            }
            if (v1) {
                ob[((size_t)oc * S + gy1) * S + gx] =
                    fmaxf(cp[2] + rc1[oc] + sBias[oc], 0.f);
                ob[((size_t)(oc + 1) * S + gy1) * S + gx] =
                    fmaxf(cp[3] + rc1[oc + 1] + sBias[oc + 1], 0.f);
            }
        }
    }
}

// ---------------- fused epilogue: 1x1 conv + sigmoid + flow + ct + grid + warp --------
__global__ __launch_bounds__(256) void k_final(const float* __restrict__ inp,
                                               const float* __restrict__ c3w,
                                               const float* __restrict__ c3b,
                                               float* __restrict__ outp) {
    __shared__ float s_w[KOBJ * 24];
    __shared__ float s_b[KOBJ];
    __shared__ float s_ot[KOBJ * 2];
    __shared__ float s_ct[2];
    int b = blockIdx.y, tid = threadIdx.x;
    int p = blockIdx.x * 256 + tid;
    for (int i = tid; i < KOBJ * 24; i += 256) s_w[i] = c3w[i];
    if (tid < KOBJ) s_b[tid] = c3b[tid];
    if (tid < KOBJ * 2) s_ot[tid] = g_ot[b * 40 + tid];
    if (tid < 2) s_ct[tid] = g_ct[b * 2 + tid];
    __syncthreads();
    if (p >= 7056) return;
    const float* mp = g_m84b + (size_t)b * 24 * 7056 + p;
    float mv[24];
    #pragma unroll
    for (int c = 0; c < 24; c++) mv[c] = mp[c * 7056];
    float fy = s_ct[0], fx = s_ct[1];
    #pragma unroll 4
    for (int k = 0; k < KOBJ; k++) {
        float s = s_b[k];
        #pragma unroll
        for (int c = 0; c < 24; c++) s += mv[c] * s_w[k * 24 + c];
        float mask = 1.f / (1.f + __expf(-s));
        fy += mask * s_ot[k * 2];
        fx += mask * s_ot[k * 2 + 1];
    }
    int gy = p / 84, gx = p % 84;
    const float isf = 0.01f * 84.0f;
    float ys = isf * fy + (float)gy;
    float xs = isf * fx + (float)gx;
    const float* src = inp + (size_t)b * 14112 + 7056;
    int x0 = min(max((int)floorf(xs), 0), 83);
    int y0 = min(max((int)floorf(ys), 0), 83);
    int x1 = min(x0 + 1, 83);
    int y1 = min(y0 + 1, 83);
    float Ia = src[y0 * 84 + x0], Ib = src[y1 * 84 + x0];
    float Ic = src[y0 * 84 + x1], Id = src[y1 * 84 + x1];
    float xc = fminf(fmaxf(xs, 0.f), 83.f);
    float yc = fminf(fmaxf(ys, 0.f), 83.f);
    float x0f = (float)x0, x1f = (float)x1, y0f = (float)y0, y1f = (float)y1;
    float o = (x1f - xc) * (y1f - yc) * Ia + (x1f - xc) * (yc - y0f) * Ib +
              (xc - x0f) * (y1f - yc) * Ic + (xc - x0f) * (yc - y0f) * Id;
    outp[(size_t)b * 7056 + p] = o;
}

// ---------------- launch ----------------
extern "C" void kernel_launch(void* const* d_in, const int* in_sizes, int n_in,
                              void* d_out, int out_size) {
    const float* inp = (const float*)d_in[0];
    const float* cw1 = (const float*)d_in[1];
    const float* cb1 = (const float*)d_in[2];
    const float* cw2 = (const float*)d_in[3];
    const float* cb2 = (const float*)d_in[4];
    const float* cw3 = (const float*)d_in[5];
    const float* cb3 = (const float*)d_in[6];
    const float* fcw = (const float*)d_in[7];
    const float* fcb = (const float*)d_in[8];
    const float* otw = (const float*)d_in[9];
    const float* otb = (const float*)d_in[10];
    const float* ctw = (const float*)d_in[11];
    const float* ctb = (const float*)d_in[12];
    const float* m1w = (const float*)d_in[13];
    const float* m1b = (const float*)d_in[14];
    const float* c1w = (const float*)d_in[15];
    const float* c1b = (const float*)d_in[16];
    const float* c2w = (const float*)d_in[17];
    const float* c2b = (const float*)d_in[18];
    const float* c3w = (const float*)d_in[19];
    const float* c3b = (const float*)d_in[20];
    float* outp = (float*)d_out;

    cudaFuncSetAttribute(k_conv1,  cudaFuncAttributeMaxDynamicSharedMemorySize, 72832);
    cudaFuncSetAttribute(k_conv23, cudaFuncAttributeMaxDynamicSharedMemorySize, 168192);
    cudaFuncSetAttribute(k_upconv_hmma, cudaFuncAttributeMaxDynamicSharedMemorySize, 85568);

    float *p_h3, *p_x, *p_fcpart, *p_m21, *p_m42b, *p_m84b;
    cudaGetSymbolAddress((void**)&p_h3,     g_h3);
    cudaGetSymbolAddress((void**)&p_x,      g_x);
    cudaGetSymbolAddress((void**)&p_fcpart, g_fcpart);
    cudaGetSymbolAddress((void**)&p_m21,    g_m21);
    cudaGetSymbolAddress((void**)&p_m42b,   g_m42b);
    cudaGetSymbolAddress((void**)&p_m84b,   g_m84b);

    // encoder
    k_conv1<<<Bsz, 256, 72832>>>(inp, cw1, cb1);
    k_conv23<<<Bsz, 256, 168192>>>(cw2, cb2, cw3, cb3);
    // fc: split-K=7 + fused reduce(relu)+heads
    k_gemm2<<<dim3(EMB / GBN, Bsz / GBM, 7), 256>>>(p_h3, fcw, fcb, p_fcpart,
                                                    Bsz, EMB, 3136, 448, 0);
    k_fcredheads<<<Bsz, 256>>>(fcb, otw, otb, ctw, ctb);
    // mask fc
    k_gemm2<<<dim3((10584 + GBN - 1) / GBN, Bsz / GBM, 1), 256>>>(p_x, m1w, m1b, p_m21,
                                                                  Bsz, 10584, EMB, EMB, 0);
    // decoder: fused upsample + residual conv via bf16 HMMA (3-term)
    // conv42: inS=21,S=42,Wp=46,npx=11,tileF=6*46*28=7728, smem=(7728+6912+32)*4=58688
    k_upconv_hmma<<<dim3(11, Bsz), 256, 58688>>>(p_m21, c1w, c1b, p_m42b,
                                                 21, 42, 46, 11, 20.f / 41.f, 7728);
    // conv84: inS=42,S=84,Wp=86,npx=21,tileF=6*86*28=14448, smem=(14448+6912+32)*4=85568
    k_upconv_hmma<<<dim3(21, Bsz), 256, 85568>>>(p_m42b, c2w, c2b, p_m84b,
                                                 42, 84, 86, 21, 41.f / 83.f, 14448);
    // fused: 1x1 conv + sigmoid masks + flow + warp
    k_final<<<dim3(28, Bsz), 256>>>(inp, c3w, c3b, outp);
    (void)in_sizes; (void)n_in; (void)out_size;
}